// round 3
// baseline (speedup 1.0000x reference)
#include <cuda_runtime.h>
#include <cuda_bf16.h>
#include <cstdint>

// Problem constants: x (12,64,256,256) f32, w (64,64,3,3) f32, out (12,64,256,256) f32
// B=4, T=3, C=64, shift=32, H=W=256, 3x3 same-pad conv of sign(x_shifted) with sign(w)*scale[o].

__device__ float g_scale[64];
__device__ uint2 g_Bpack[9 * 4 * 8 * 32];   // [tap][ktile][ntile][lane] -> (b0,b1) regs, 73728 B

__device__ __forceinline__ uint32_t sign_bf16_bits(float x) {
    uint32_t u = __float_as_uint(x);
    uint32_t mag = u & 0x7FFFFFFFu;
    uint32_t s = (u >> 16) & 0x8000u;
    return mag ? (0x3F80u | s) : 0u;     // +-1.0 in bf16, 0 if x==0
}

// -------------------- weight prep --------------------

__global__ void prep_scale_kernel(const float* __restrict__ w) {
    int o = blockIdx.x;           // 64 blocks
    int tid = threadIdx.x;        // 256
    float s = 0.f;
    for (int i = tid; i < 576; i += 256) s += fabsf(w[o * 576 + i]);
    #pragma unroll
    for (int off = 16; off; off >>= 1) s += __shfl_down_sync(0xFFFFFFFFu, s, off);
    __shared__ float red[8];
    if ((tid & 31) == 0) red[tid >> 5] = s;
    __syncthreads();
    if (tid < 8) {
        float v = red[tid];
        #pragma unroll
        for (int off = 4; off; off >>= 1) v += __shfl_down_sync(0xFFu, v, off);
        if (tid == 0) g_scale[o] = v * (1.0f / 576.0f);
    }
}

// Pack sign(w) into the exact mma.m16n8k16 B-fragment register layout:
// lane: tig = lane&3, g = lane>>2; b0 = {B[2tig][g], B[2tig+1][g]}, b1 = {B[2tig+8][g], B[2tig+9][g]}
// with B[k][n] = sign(w[o = nt*8+n][c = kt*16+k][kh][kw]).
__global__ void prep_weights_kernel(const float* __restrict__ w) {
    int tap = blockIdx.x;         // 0..8  (kh*3+kw)
    int kt  = blockIdx.y;         // 0..3
    int tid = threadIdx.x;        // 256
    int nt   = tid >> 5;
    int lane = tid & 31;
    int tig  = lane & 3;
    int g    = lane >> 2;
    int o = nt * 8 + g;

    uint32_t e[4];
    #pragma unroll
    for (int j = 0; j < 4; j++) {
        int k = (j < 2) ? (2 * tig + j) : (2 * tig + 8 + (j - 2));
        int c = kt * 16 + k;
        e[j] = sign_bf16_bits(w[(o * 64 + c) * 9 + tap]);
    }
    uint32_t b0 = e[0] | (e[1] << 16);
    uint32_t b1 = e[2] | (e[3] << 16);
    g_Bpack[((tap * 4 + kt) * 8 + nt) * 32 + lane] = make_uint2(b0, b1);
}

// -------------------- fused shift+sign+conv --------------------
// CTA tile: 4 rows x 32 cols of output pixels (M=128), all 64 out channels (N=64), K=576.
// smem: input sign tile [204 pixels][64 ch] bf16, xor-swizzled (26112 B)
//       + packed B (73728 B) + scales (256 B) = 100096 B dynamic.

#define SMEM_IN_BYTES   (204 * 128)
#define SMEM_B_OFF      SMEM_IN_BYTES
#define SMEM_SC_OFF     (SMEM_IN_BYTES + 73728)
#define SMEM_TOTAL      (SMEM_SC_OFF + 256)

__global__ void __launch_bounds__(256, 2)
conv_kernel(const float* __restrict__ x, float* __restrict__ out) {
    extern __shared__ unsigned char smem[];
    unsigned char* sIn = smem;
    uint2* sB    = reinterpret_cast<uint2*>(smem + SMEM_B_OFF);
    float* sScale = reinterpret_cast<float*>(smem + SMEM_SC_OFF);

    const int tid = threadIdx.x;
    const int bt = blockIdx.z;            // 0..11
    const int h0 = blockIdx.y * 4;
    const int w0 = blockIdx.x * 32;
    const int b = bt / 3, t = bt % 3;

    // ---- stage packed B into smem (4608 uint4) ----
    {
        const uint4* src = reinterpret_cast<const uint4*>(g_Bpack);
        uint4* dst = reinterpret_cast<uint4*>(sB);
        #pragma unroll
        for (int k = 0; k < 18; k++) dst[tid + k * 256] = src[tid + k * 256];
    }
    if (tid < 64) sScale[tid] = g_scale[tid];

    // ---- load input tile (with halo) -> sign bf16, channel-shifted, swizzled ----
    // pixels: 6 rows x 34 cols = 204; layout [pixel][64ch], byte = pix*128 + (2c ^ ((pix&7)<<4))
    if (tid < 204) {
        int pr = tid / 34, pc = tid - pr * 34;
        int h  = h0 - 1 + pr;
        int ww = w0 - 1 + pc;
        bool valid = ((unsigned)h < 256u) && ((unsigned)ww < 256u);
        int hw = h * 256 + ww;
        #pragma unroll
        for (int gq = 0; gq < 8; gq++) {       // 8 channels per STS.128
            uint32_t pk[4];
            #pragma unroll
            for (int j2 = 0; j2 < 4; j2++) {
                uint32_t lo = 0, hi = 0;
                {
                    int c = gq * 8 + j2 * 2;
                    int flat = t * 64 + c - 32; if (flat < 0) flat += 192;
                    if (valid) lo = sign_bf16_bits(x[(long)(b * 192 + flat) * 65536 + hw]);
                }
                {
                    int c = gq * 8 + j2 * 2 + 1;
                    int flat = t * 64 + c - 32; if (flat < 0) flat += 192;
                    if (valid) hi = sign_bf16_bits(x[(long)(b * 192 + flat) * 65536 + hw]);
                }
                pk[j2] = lo | (hi << 16);
            }
            uint32_t byteoff = (uint32_t)tid * 128u + (((uint32_t)gq * 16u) ^ (((uint32_t)tid & 7u) << 4));
            *reinterpret_cast<uint4*>(sIn + byteoff) = make_uint4(pk[0], pk[1], pk[2], pk[3]);
        }
    }
    __syncthreads();

    // ---- mainloop: 9 taps x 4 ktiles; per warp: 1 ldmatrix.x4 (A) + 8 x (LDS.64 B + mma) ----
    const int warp = tid >> 5, lane = tid & 31;
    const int ph  = warp >> 1;            // tile row 0..3
    const int pw0 = (warp & 1) * 16;      // tile col base 0 / 16
    const int tig = lane & 3, g = lane >> 2;
    const int mrow  = lane & 15;          // ldmatrix row (pixel within m16)
    const int khalf = lane >> 4;          // k-halves

    float acc[8][4];
    #pragma unroll
    for (int nt = 0; nt < 8; nt++) {
        acc[nt][0] = 0.f; acc[nt][1] = 0.f; acc[nt][2] = 0.f; acc[nt][3] = 0.f;
    }

    const uint32_t sIn_base = (uint32_t)__cvta_generic_to_shared(sIn);

    #pragma unroll
    for (int tap = 0; tap < 9; tap++) {
        const int kh = tap / 3, kw = tap - kh * 3;
        // this thread's ldmatrix row pixel: (ph+kh, pw0+kw+mrow) in the 6x34 halo tile
        const int pix = (ph + kh) * 34 + pw0 + kw + mrow;
        const uint32_t pix_sw = ((uint32_t)pix & 7u) << 4;
        #pragma unroll
        for (int kt = 0; kt < 4; kt++) {
            uint32_t a0, a1, a2, a3;
            uint32_t addr = sIn_base + (uint32_t)pix * 128u
                          + (((uint32_t)(kt * 32 + khalf * 16)) ^ pix_sw);
            asm volatile("ldmatrix.sync.aligned.x4.m8n8.shared.b16 {%0,%1,%2,%3}, [%4];"
                         : "=r"(a0), "=r"(a1), "=r"(a2), "=r"(a3) : "r"(addr));
            #pragma unroll
            for (int nt = 0; nt < 8; nt++) {
                uint2 bb = sB[((tap * 4 + kt) * 8 + nt) * 32 + lane];
                asm volatile(
                    "mma.sync.aligned.m16n8k16.row.col.f32.bf16.bf16.f32 "
                    "{%0,%1,%2,%3}, {%4,%5,%6,%7}, {%8,%9}, {%0,%1,%2,%3};"
                    : "+f"(acc[nt][0]), "+f"(acc[nt][1]), "+f"(acc[nt][2]), "+f"(acc[nt][3])
                    : "r"(a0), "r"(a1), "r"(a2), "r"(a3), "r"(bb.x), "r"(bb.y));
            }
        }
    }

    // ---- epilogue: D(m,n): d0=(g,2tig) d1=(g,2tig+1) d2=(g+8,2tig) d3=(g+8,2tig+1) ----
    const int hh = h0 + ph;
    const int wb = w0 + pw0 + g;
    #pragma unroll
    for (int nt = 0; nt < 8; nt++) {
        int o0 = nt * 8 + 2 * tig;
        float s0 = sScale[o0], s1 = sScale[o0 + 1];
        long base0 = ((long)(bt * 64 + o0) << 16) + (hh << 8) + wb;
        long base1 = base0 + 65536;
        out[base0]     = s0 * acc[nt][0];
        out[base1]     = s1 * acc[nt][1];
        out[base0 + 8] = s0 * acc[nt][2];
        out[base1 + 8] = s1 * acc[nt][3];
    }
}

// -------------------- launch --------------------

extern "C" void kernel_launch(void* const* d_in, const int* in_sizes, int n_in,
                              void* d_out, int out_size) {
    const float* x = (const float*)d_in[0];   // (12,64,256,256)
    const float* w = (const float*)d_in[1];   // (64,64,3,3)
    float* out = (float*)d_out;

    cudaFuncSetAttribute(conv_kernel, cudaFuncAttributeMaxDynamicSharedMemorySize, SMEM_TOTAL);

    prep_scale_kernel<<<64, 256>>>(w);
    prep_weights_kernel<<<dim3(9, 4, 1), 256>>>(w);
    conv_kernel<<<dim3(8, 64, 12), 256, SMEM_TOTAL>>>(x, out);
}